// round 7
// baseline (speedup 1.0000x reference)
#include <cuda_runtime.h>
#include <math.h>
#include <stdint.h>

#define NN 50000      // nodes
#define NE 800000     // edges
#define NG 128        // graphs
#define FX 92         // node feature dim
#define FE 41         // edge feature dim
#define HD 64         // hidden
#define NCV 3         // conv layers
#define BN_EPS 1e-5f
#define NBLK 196      // scan blocks: 196*256 = 50176 >= NN
#define EPT 128       // edges per tile

typedef unsigned long long ull;
typedef long long ll;

// ---------------- device scratch ----------------
__device__ float g_h[NN * HD];
__device__ float g_acc[NN * HD];
__device__ float g_HN[NN * 4 * HD];                   // [N,256]: [f_i|s_i|f_j|s_j]
__device__ float g_Wce[NCV * FE * 2 * HD];
__device__ float g_bce[NCV * 2 * HD];
__device__ float g_Wnode[NCV * HD * 4 * HD];
__device__ float g_sum[NCV * HD];
__device__ float g_sumsq[NCV * HD];
__device__ float g_gsum[NG * HD];
__device__ float g_gcnt[NG];
// sort-by-dst machinery
__device__ int   g_deg[NN];
__device__ int   g_cursor[NN];
__device__ int   g_rp[NN];
__device__ int   g_bsum[256];
__device__ int   g_perm[NE];
__device__ int   g_srcp[NE];
__device__ int   g_dstp[NE];
__device__ float g_eap[(ll)NE * FE];   // permuted edge_attr

// ---------------- helpers ----------------
__device__ __forceinline__ ull pack2(float a, float b) {
    ull r; asm("mov.b64 %0, {%1, %2};" : "=l"(r) : "f"(a), "f"(b)); return r;
}
__device__ __forceinline__ void unpack2(ull v, float& a, float& b) {
    asm("mov.b64 {%0, %1}, %2;" : "=f"(a), "=f"(b) : "l"(v));
}
__device__ __forceinline__ void fma2(ull& d, ull a, ull b) {
    asm("fma.rn.f32x2 %0, %1, %2, %0;" : "+l"(d) : "l"(a), "l"(b));
}
__device__ __forceinline__ float sigmoid_f(float x) {
    return __fdividef(1.0f, 1.0f + __expf(-x));
}
__device__ __forceinline__ float softplus_f(float x) {
    return fmaxf(x, 0.0f) + __logf(1.0f + __expf(-fabsf(x)));
}
__device__ __forceinline__ void red4(float* p, float4 v) {
    asm volatile("red.global.add.v4.f32 [%0], {%1,%2,%3,%4};"
                 :: "l"(p), "f"(v.x), "f"(v.y), "f"(v.z), "f"(v.w) : "memory");
}
__device__ __forceinline__ void red2(float* p, float a, float b) {
    asm volatile("red.global.add.v2.f32 [%0], {%1,%2};"
                 :: "l"(p), "f"(a), "f"(b) : "memory");
}
__device__ __forceinline__ uint32_t to_tf32(float f) {
    uint32_t r; asm("cvt.rna.tf32.f32 %0, %1;" : "=r"(r) : "f"(f)); return r;
}
__device__ __forceinline__ void mma_tf32(float c[4], uint32_t a0, uint32_t a1,
                                         uint32_t a2, uint32_t a3,
                                         uint32_t b0, uint32_t b1) {
    asm volatile(
        "mma.sync.aligned.m16n8k8.row.col.f32.tf32.tf32.f32 "
        "{%0,%1,%2,%3}, {%4,%5,%6,%7}, {%8,%9}, {%0,%1,%2,%3};"
        : "+f"(c[0]), "+f"(c[1]), "+f"(c[2]), "+f"(c[3])
        : "r"(a0), "r"(a1), "r"(a2), "r"(a3), "r"(b0), "r"(b1));
}

// ---------------- prep: fold weights ----------------
__global__ void prep_kernel(const float* __restrict__ W_emb2, const float* __restrict__ b_emb2,
                            const float* __restrict__ Wf, const float* __restrict__ bf,
                            const float* __restrict__ Ws, const float* __restrict__ bs) {
    int idx = blockIdx.x * blockDim.x + threadIdx.x;
    const int N_WCE = NCV * FE * 2 * HD;
    const int N_BCE = NCV * 2 * HD;
    const int N_WND = NCV * HD * 4 * HD;
    if (idx < N_WCE) {
        int j = idx % (2 * HD);
        int k = (idx / (2 * HD)) % FE;
        int a = idx / (2 * HD * FE);
        const float* Wb = (j < HD) ? Wf : Ws;
        int jj = j & (HD - 1);
        float s = 0.f;
        #pragma unroll 8
        for (int m = 0; m < HD; m++)
            s = fmaf(W_emb2[k * HD + m], Wb[(a * 3 * HD + 2 * HD + m) * HD + jj], s);
        g_Wce[idx] = s;
    } else if (idx < N_WCE + N_BCE) {
        int t = idx - N_WCE;
        int j = t % (2 * HD);
        int a = t / (2 * HD);
        const float* Wb = (j < HD) ? Wf : Ws;
        const float* bb = (j < HD) ? bf : bs;
        int jj = j & (HD - 1);
        float s = bb[a * HD + jj];
        #pragma unroll 8
        for (int m = 0; m < HD; m++)
            s = fmaf(b_emb2[m], Wb[(a * 3 * HD + 2 * HD + m) * HD + jj], s);
        g_bce[t] = s;
    } else if (idx < N_WCE + N_BCE + N_WND) {
        int t = idx - N_WCE - N_BCE;
        int j = t % (4 * HD);
        int m = (t / (4 * HD)) % HD;
        int a = t / (4 * HD * HD);
        int blk = j / HD;                 // 0:f_i 1:s_i 2:f_j 3:s_j
        int jj = j & (HD - 1);
        const float* Wsel = (blk & 1) ? Ws : Wf;
        int roff = (blk >= 2) ? HD : 0;
        g_Wnode[t] = Wsel[(a * 3 * HD + roff + m) * HD + jj];
    }
}

// ---------------- zero counters/stats ----------------
__global__ void zero_kernel() {
    int i = blockIdx.x * blockDim.x + threadIdx.x;
    if (i < NN) { g_deg[i] = 0; g_cursor[i] = 0; }
    if (i < NCV * HD) { g_sum[i] = 0.f; g_sumsq[i] = 0.f; }
    if (i < NG * HD) g_gsum[i] = 0.f;
    if (i < NG) g_gcnt[i] = 0.f;
}

// ---------------- sort by dst ----------------
__global__ void hist_kernel(const int* __restrict__ ei) {
    int e = blockIdx.x * blockDim.x + threadIdx.x;
    if (e < NE) atomicAdd(&g_deg[ei[NE + e]], 1);
}
__global__ void scan1_kernel() {
    __shared__ int s[256];
    int tid = threadIdx.x;
    int i = blockIdx.x * 256 + tid;
    int v = (i < NN) ? g_deg[i] : 0;
    s[tid] = v; __syncthreads();
    #pragma unroll
    for (int off = 1; off < 256; off <<= 1) {
        int t = (tid >= off) ? s[tid - off] : 0;
        __syncthreads();
        s[tid] += t;
        __syncthreads();
    }
    if (i < NN) g_rp[i] = s[tid] - v;
    if (tid == 255) g_bsum[blockIdx.x] = s[255];
}
__global__ void scan2_kernel() {
    __shared__ int s[256];
    int tid = threadIdx.x;
    int v = (tid < NBLK) ? g_bsum[tid] : 0;
    s[tid] = v; __syncthreads();
    #pragma unroll
    for (int off = 1; off < 256; off <<= 1) {
        int t = (tid >= off) ? s[tid - off] : 0;
        __syncthreads();
        s[tid] += t;
        __syncthreads();
    }
    if (tid < NBLK) g_bsum[tid] = s[tid] - v;
}
__global__ void scan3_kernel() {
    int i = blockIdx.x * 256 + threadIdx.x;
    if (i < NN) g_rp[i] += g_bsum[blockIdx.x];
}
__global__ void scatter_kernel(const int* __restrict__ ei) {
    int e = blockIdx.x * blockDim.x + threadIdx.x;
    if (e >= NE) return;
    int d = ei[NE + e];
    int s = ei[e];
    int pos = g_rp[d] + atomicAdd(&g_cursor[d], 1);
    g_perm[pos] = e;
    g_srcp[pos] = s;
    g_dstp[pos] = d;
}
__global__ void permute_ea_kernel(const float* __restrict__ ea) {
    int w = (blockIdx.x * blockDim.x + threadIdx.x) >> 5;
    int lane = threadIdx.x & 31;
    int nw = (gridDim.x * blockDim.x) >> 5;
    for (int row = w; row < NE; row += nw) {
        int e = g_perm[row];
        for (int k = lane; k < FE; k += 32)
            g_eap[(ll)row * FE + k] = ea[(ll)e * FE + k];
    }
}

// ---------------- generic fp32 GEMM with f32x2 inner loop ----------------
template <int K, int NC, int CT, int RT, int RPT>
__global__ void gemm_bias_kernel(const float* __restrict__ A, const float* __restrict__ B,
                                 const float* __restrict__ bias, float* __restrict__ C,
                                 int M, int ldb, int ldc) {
    constexpr int TR = RT * RPT;
    constexpr int KP = K + 1;
    constexpr int NT = CT * RT;
    extern __shared__ float smem[];
    float* Bs = smem;
    float* As = smem + K * NC;
    int tid = threadIdx.x;
    int tx = tid % CT;
    int ty = tid / CT;
    int c0 = blockIdx.y * NC;
    for (int i = tid; i < K * NC; i += NT) {
        int k = i / NC, c = i - k * NC;
        Bs[i] = B[k * ldb + c0 + c];
    }
    ull bp[4];
    #pragma unroll
    for (int c = 0; c < 4; c++) {
        float b0 = bias ? bias[c0 + tx * 8 + 2 * c] : 0.f;
        float b1 = bias ? bias[c0 + tx * 8 + 2 * c + 1] : 0.f;
        bp[c] = pack2(b0, b1);
    }
    for (int tile = blockIdx.x; (ll)tile * TR < M; tile += gridDim.x) {
        int row0 = tile * TR;
        __syncthreads();
        for (int i = tid; i < TR * K; i += NT) {
            int r = i / K;
            int k = i - r * K;
            int gr = row0 + r;
            As[r * KP + k] = (gr < M) ? A[(ll)gr * K + k] : 0.f;
        }
        __syncthreads();
        ull acc[RPT][4];
        #pragma unroll
        for (int r = 0; r < RPT; r++)
            #pragma unroll
            for (int c = 0; c < 4; c++) acc[r][c] = bp[c];
        for (int k = 0; k < K; k++) {
            float4 b0 = *reinterpret_cast<const float4*>(&Bs[k * NC + tx * 8]);
            float4 b1 = *reinterpret_cast<const float4*>(&Bs[k * NC + tx * 8 + 4]);
            ull p0 = pack2(b0.x, b0.y), p1 = pack2(b0.z, b0.w);
            ull p2 = pack2(b1.x, b1.y), p3 = pack2(b1.z, b1.w);
            #pragma unroll
            for (int r = 0; r < RPT; r++) {
                float a = As[(ty * RPT + r) * KP + k];
                ull ad = pack2(a, a);
                fma2(acc[r][0], ad, p0);
                fma2(acc[r][1], ad, p1);
                fma2(acc[r][2], ad, p2);
                fma2(acc[r][3], ad, p3);
            }
        }
        #pragma unroll
        for (int r = 0; r < RPT; r++) {
            int gr = row0 + ty * RPT + r;
            if (gr < M) {
                float o[8];
                #pragma unroll
                for (int c = 0; c < 4; c++) unpack2(acc[r][c], o[2 * c], o[2 * c + 1]);
                float* cp = &C[(ll)gr * ldc + c0 + tx * 8];
                *reinterpret_cast<float4*>(cp) = make_float4(o[0], o[1], o[2], o[3]);
                *reinterpret_cast<float4*>(cp + 4) = make_float4(o[4], o[5], o[6], o[7]);
            }
        }
    }
}

// ---------------- residual copy ----------------
__global__ void copy_kernel() {
    int idx4 = blockIdx.x * blockDim.x + threadIdx.x;
    if (idx4 < NN * 16)
        reinterpret_cast<float4*>(g_acc)[idx4] = reinterpret_cast<const float4*>(g_h)[idx4];
}

// ---------------- fused: mma.sync tf32 edge GEMM + message + CSR scatter ----------------
// smem layout (bytes):
//   [0,512)       bias[128]
//   [512,1024)    src[128]
//   [1024,1536)   dst[128]
//   [1536, +48*136*4)   At: A transposed, tf32 bits  (26112B)
//   [27648, +3072*8)    Bp: prepacked B fragments    (24576B)
//   [52224, +128*132*4) EW tile                      (67584B)
#define AT_LD  136
#define EW_LD  132
#define SM_AT  1536
#define SM_BP  (SM_AT + 48 * AT_LD * 4)
#define SM_EW  (SM_BP + 3072 * 8)
#define FE_SMEM (SM_EW + EPT * EW_LD * 4)

__global__ __launch_bounds__(256, 1) void fused_edge_kernel(
        const float* __restrict__ Wce, const float* __restrict__ bce) {
    extern __shared__ char base[];
    float*    bias_s = (float*)(base);
    int*      src_s  = (int*)(base + 512);
    int*      dst_s  = (int*)(base + 1024);
    uint32_t* At     = (uint32_t*)(base + SM_AT);
    uint2*    Bp     = (uint2*)(base + SM_BP);
    float*    EW_s   = (float*)(base + SM_EW);

    int tid = threadIdx.x;
    int lane = tid & 31, wid = tid >> 5;
    int gid = lane >> 2, tig = lane & 3;

    if (tid < 128) bias_s[tid] = bce[tid];
    // zero k-padding rows 41..47 of At (never rewritten)
    for (int i = tid; i < 7 * AT_LD; i += 256) At[FE * AT_LD + i] = 0u;
    // prepack B fragments: Bp[(kk*16+nt)*32+lane] = {B[8kk+tig][8nt+gid], B[8kk+tig+4][8nt+gid]}
    for (int i = tid; i < 3072; i += 256) {
        int l = i & 31, nt = (i >> 5) & 15, kk = i >> 9;
        int g = l >> 2, t = l & 3;
        int k0 = 8 * kk + t, k1 = k0 + 4, n = 8 * nt + g;
        uint32_t b0 = (k0 < FE) ? to_tf32(Wce[k0 * 128 + n]) : 0u;
        uint32_t b1 = (k1 < FE) ? to_tf32(Wce[k1 * 128 + n]) : 0u;
        Bp[i] = make_uint2(b0, b1);
    }

    const int ntiles = NE / EPT;   // 6250
    int row0 = wid * 16;
    for (int tile = blockIdx.x; tile < ntiles; tile += gridDim.x) {
        int e0 = tile * EPT;
        __syncthreads();   // prev msg phase done before At/EW overwrite
        // stage A transposed + tf32-converted: At[k][e]
        for (int i = tid; i < EPT * FE; i += 256) {
            int r = i / FE, k = i - r * FE;
            At[k * AT_LD + r] = to_tf32(g_eap[(ll)e0 * FE + i]);
        }
        if (tid < EPT) {
            src_s[tid] = g_srcp[e0 + tid];
            dst_s[tid] = g_dstp[e0 + tid];
        }
        __syncthreads();

        // ---- mma phase: warp computes rows [row0,row0+16) x 128 cols ----
        {
            float c[16][4];
            #pragma unroll
            for (int nt = 0; nt < 16; nt++)
                #pragma unroll
                for (int q = 0; q < 4; q++) c[nt][q] = 0.f;
            #pragma unroll
            for (int kk = 0; kk < 6; kk++) {
                uint32_t a0 = At[(8 * kk + tig) * AT_LD + row0 + gid];
                uint32_t a1 = At[(8 * kk + tig) * AT_LD + row0 + gid + 8];
                uint32_t a2 = At[(8 * kk + tig + 4) * AT_LD + row0 + gid];
                uint32_t a3 = At[(8 * kk + tig + 4) * AT_LD + row0 + gid + 8];
                #pragma unroll
                for (int nt = 0; nt < 16; nt++) {
                    uint2 b = Bp[(kk * 16 + nt) * 32 + lane];
                    mma_tf32(c[nt], a0, a1, a2, a3, b.x, b.y);
                }
            }
            // store C + bias to EW (transpose to row-major per edge)
            #pragma unroll
            for (int nt = 0; nt < 16; nt++) {
                float2 bi = *reinterpret_cast<const float2*>(&bias_s[nt * 8 + 2 * tig]);
                *reinterpret_cast<float2*>(&EW_s[(row0 + gid) * EW_LD + nt * 8 + 2 * tig]) =
                    make_float2(c[nt][0] + bi.x, c[nt][1] + bi.y);
                *reinterpret_cast<float2*>(&EW_s[(row0 + gid + 8) * EW_LD + nt * 8 + 2 * tig]) =
                    make_float2(c[nt][2] + bi.x, c[nt][3] + bi.y);
            }
        }
        __syncthreads();

        // ---- message phase: warp handles edges [row0,row0+16), run-compressed ----
        {
            float2 fj[16], sj[16];
            #pragma unroll
            for (int r = 0; r < 16; r++) {
                int s = src_s[row0 + r];
                fj[r] = *reinterpret_cast<const float2*>(&g_HN[(ll)s * 256 + 128 + 2 * lane]);
                sj[r] = *reinterpret_cast<const float2*>(&g_HN[(ll)s * 256 + 192 + 2 * lane]);
            }
            int dprev = -1;
            float fi0 = 0.f, fi1 = 0.f, si0 = 0.f, si1 = 0.f, a0 = 0.f, a1 = 0.f;
            #pragma unroll
            for (int r = 0; r < 16; r++) {
                int e = row0 + r;
                int d = dst_s[e];   // warp-uniform
                if (d != dprev) {
                    if (dprev >= 0) red2(&g_acc[(ll)dprev * HD + 2 * lane], a0, a1);
                    float2 t0 = *reinterpret_cast<const float2*>(&g_HN[(ll)d * 256 + 2 * lane]);
                    float2 t1 = *reinterpret_cast<const float2*>(&g_HN[(ll)d * 256 + 64 + 2 * lane]);
                    fi0 = t0.x; fi1 = t0.y; si0 = t1.x; si1 = t1.y;
                    a0 = 0.f; a1 = 0.f;
                    dprev = d;
                }
                float2 ef = *reinterpret_cast<const float2*>(&EW_s[e * EW_LD + 2 * lane]);
                float2 es = *reinterpret_cast<const float2*>(&EW_s[e * EW_LD + 64 + 2 * lane]);
                a0 += sigmoid_f(ef.x + fi0 + fj[r].x) * softplus_f(es.x + si0 + sj[r].x);
                a1 += sigmoid_f(ef.y + fi1 + fj[r].y) * softplus_f(es.y + si1 + sj[r].y);
            }
            if (dprev >= 0) red2(&g_acc[(ll)dprev * HD + 2 * lane], a0, a1);
        }
    }
}

// ---------------- BN stats ----------------
__global__ void stats_kernel(int a) {
    __shared__ float s_s[HD], s_q[HD];
    int tid = threadIdx.x;
    if (tid < HD) { s_s[tid] = 0.f; s_q[tid] = 0.f; }
    __syncthreads();
    int col4 = tid & 15;
    float4 ls = make_float4(0.f, 0.f, 0.f, 0.f), lq = ls;
    const float4* acc4 = reinterpret_cast<const float4*>(g_acc);
    for (int idx4 = blockIdx.x * blockDim.x + tid; idx4 < NN * 16; idx4 += gridDim.x * blockDim.x) {
        float4 v = acc4[idx4];
        ls.x += v.x; lq.x = fmaf(v.x, v.x, lq.x);
        ls.y += v.y; lq.y = fmaf(v.y, v.y, lq.y);
        ls.z += v.z; lq.z = fmaf(v.z, v.z, lq.z);
        ls.w += v.w; lq.w = fmaf(v.w, v.w, lq.w);
    }
    atomicAdd(&s_s[col4 * 4 + 0], ls.x); atomicAdd(&s_q[col4 * 4 + 0], lq.x);
    atomicAdd(&s_s[col4 * 4 + 1], ls.y); atomicAdd(&s_q[col4 * 4 + 1], lq.y);
    atomicAdd(&s_s[col4 * 4 + 2], ls.z); atomicAdd(&s_q[col4 * 4 + 2], lq.z);
    atomicAdd(&s_s[col4 * 4 + 3], ls.w); atomicAdd(&s_q[col4 * 4 + 3], lq.w);
    __syncthreads();
    if (tid < HD) {
        atomicAdd(&g_sum[a * HD + tid], s_s[tid]);
        atomicAdd(&g_sumsq[a * HD + tid], s_q[tid]);
    }
}

// ---------------- BN normalize (+relu) (+next residual) (+pooling) ----------------
__global__ void bn_kernel(const float* __restrict__ gamma, const float* __restrict__ beta,
                          int a, int do_relu, int write_acc, int do_pool,
                          const int* __restrict__ batch) {
    int idx4 = blockIdx.x * blockDim.x + threadIdx.x;
    if (idx4 >= NN * 16) return;
    int col4 = idx4 & 15;
    int node = idx4 >> 4;
    const float invn = 1.0f / (float)NN;
    float4 su = reinterpret_cast<const float4*>(g_sum)[a * 16 + col4];
    float4 sq = reinterpret_cast<const float4*>(g_sumsq)[a * 16 + col4];
    float4 ga = reinterpret_cast<const float4*>(gamma)[col4];
    float4 be = reinterpret_cast<const float4*>(beta)[col4];
    float4 v = reinterpret_cast<const float4*>(g_acc)[idx4];
    #pragma unroll
    for (int c = 0; c < 4; c++) {
        float mu = (&su.x)[c] * invn;
        float var = fmaxf((&sq.x)[c] * invn - mu * mu, 0.f);
        float y = ((&v.x)[c] - mu) * rsqrtf(var + BN_EPS) * (&ga.x)[c] + (&be.x)[c];
        if (do_relu) y = fmaxf(y, 0.f);
        (&v.x)[c] = y;
    }
    reinterpret_cast<float4*>(g_h)[idx4] = v;
    if (write_acc) reinterpret_cast<float4*>(g_acc)[idx4] = v;
    if (do_pool) {
        int b = batch[node];
        red4(&g_gsum[b * HD + col4 * 4], v);
        if (col4 == 0) atomicAdd(&g_gcnt[b], 1.0f);
    }
}

// ---------------- final MLP ----------------
__global__ void mlp_kernel(const float* __restrict__ W1, const float* __restrict__ b1,
                           const float* __restrict__ W2, const float* __restrict__ b2,
                           const float* __restrict__ Wo, const float* __restrict__ bo,
                           float* __restrict__ out) {
    __shared__ float sW1[HD * HD], sW2[HD * HD], sWo[HD], sb1[HD], sb2[HD];
    int tid = threadIdx.x;
    for (int i = tid; i < HD * HD; i += blockDim.x) { sW1[i] = W1[i]; sW2[i] = W2[i]; }
    if (tid < HD) { sWo[tid] = Wo[tid]; sb1[tid] = b1[tid]; sb2[tid] = b2[tid]; }
    __syncthreads();
    if (tid < NG) {
        float inv = 1.0f / fmaxf(g_gcnt[tid], 1.0f);
        float v[HD], y[HD];
        #pragma unroll
        for (int k = 0; k < HD; k++) v[k] = g_gsum[tid * HD + k] * inv;
        #pragma unroll 1
        for (int j = 0; j < HD; j++) {
            float s = sb1[j];
            #pragma unroll
            for (int k = 0; k < HD; k++) s = fmaf(v[k], sW1[k * HD + j], s);
            y[j] = softplus_f(s);
        }
        float o = bo[0];
        #pragma unroll 1
        for (int j = 0; j < HD; j++) {
            float s = sb2[j];
            #pragma unroll
            for (int k = 0; k < HD; k++) s = fmaf(y[k], sW2[k * HD + j], s);
            o = fmaf(softplus_f(s), sWo[j], o);
        }
        out[tid] = o;
    }
}

// ---------------- host launcher ----------------
template <int K, int NC, int CT, int RT, int RPT>
static void launch_gemm(const float* A, const float* B, const float* bias, float* C,
                        int M, int ldb, int ldc, int nsplit) {
    constexpr int TR = RT * RPT;
    constexpr int KP = K + 1;
    static_assert(CT * 8 == NC, "col threads x 8 must equal NC");
    size_t sm = (size_t)(K * NC + TR * KP) * sizeof(float);
    if (sm > 48 * 1024) {
        cudaFuncSetAttribute(gemm_bias_kernel<K, NC, CT, RT, RPT>,
                             cudaFuncAttributeMaxDynamicSharedMemorySize, (int)sm);
    }
    dim3 grid((M + TR - 1) / TR, nsplit);
    gemm_bias_kernel<K, NC, CT, RT, RPT><<<grid, CT * RT, sm>>>(A, B, bias, C, M, ldb, ldc);
}

extern "C" void kernel_launch(void* const* d_in, const int* in_sizes, int n_in,
                              void* d_out, int out_size) {
    const float* x         = (const float*)d_in[0];
    const float* edge_attr = (const float*)d_in[1];
    const int*   ei        = (const int*)d_in[2];
    const int*   batch     = (const int*)d_in[3];
    const float* W_emb1    = (const float*)d_in[4];
    const float* b_emb1    = (const float*)d_in[5];
    const float* W_emb2    = (const float*)d_in[6];
    const float* b_emb2    = (const float*)d_in[7];
    const float* Wf        = (const float*)d_in[8];
    const float* bf        = (const float*)d_in[9];
    const float* Ws        = (const float*)d_in[10];
    const float* bs        = (const float*)d_in[11];
    const float* gamma     = (const float*)d_in[12];
    const float* beta      = (const float*)d_in[13];
    const float* W1        = (const float*)d_in[14];
    const float* b1        = (const float*)d_in[15];
    const float* W2        = (const float*)d_in[16];
    const float* b2        = (const float*)d_in[17];
    const float* Wo        = (const float*)d_in[18];
    const float* bo        = (const float*)d_in[19];
    float* out = (float*)d_out;

    float *p_h, *p_Wce, *p_bce, *p_Wnode, *p_HN;
    cudaGetSymbolAddress((void**)&p_h, g_h);
    cudaGetSymbolAddress((void**)&p_Wce, g_Wce);
    cudaGetSymbolAddress((void**)&p_bce, g_bce);
    cudaGetSymbolAddress((void**)&p_Wnode, g_Wnode);
    cudaGetSymbolAddress((void**)&p_HN, g_HN);

    // fold weights + zero counters/stats
    prep_kernel<<<255, 256>>>(W_emb2, b_emb2, Wf, bf, Ws, bs);
    zero_kernel<<<NBLK, 256>>>();

    // sort edges by dst (counting sort) + permute edge_attr
    hist_kernel<<<(NE + 255) / 256, 256>>>(ei);
    scan1_kernel<<<NBLK, 256>>>();
    scan2_kernel<<<1, 256>>>();
    scan3_kernel<<<NBLK, 256>>>();
    scatter_kernel<<<(NE + 255) / 256, 256>>>(ei);
    permute_ea_kernel<<<1600, 256>>>(edge_attr);

    // h0 = x @ W_emb1 + b_emb1
    launch_gemm<FX, HD, 8, 32, 4>(x, W_emb1, b_emb1, p_h, NN, HD, HD, 1);
    copy_kernel<<<(NN * 16 + 255) / 256, 256>>>();

    cudaFuncSetAttribute(fused_edge_kernel,
                         cudaFuncAttributeMaxDynamicSharedMemorySize, FE_SMEM);

    for (int a = 0; a < NCV; a++) {
        launch_gemm<HD, 2 * HD, 16, 16, 8>(p_h, p_Wnode + (ll)a * HD * 4 * HD,
                                           nullptr, p_HN, NN, 4 * HD, 4 * HD, 2);
        fused_edge_kernel<<<148, 256, FE_SMEM>>>(p_Wce + a * FE * 2 * HD,
                                                 p_bce + a * 2 * HD);
        stats_kernel<<<296, 256>>>(a);
        bn_kernel<<<(NN * 16 + 255) / 256, 256>>>(gamma + a * HD, beta + a * HD, a,
                                                  a < NCV - 1 ? 1 : 0,
                                                  a < NCV - 1 ? 1 : 0,
                                                  a == NCV - 1 ? 1 : 0, batch);
    }

    mlp_kernel<<<1, 128>>>(W1, b1, W2, b2, Wo, bo, out);
}

// round 8
// speedup vs baseline: 1.2836x; 1.2836x over previous
#include <cuda_runtime.h>
#include <math.h>
#include <stdint.h>

#define NN 50000      // nodes
#define NE 800000     // edges
#define NG 128        // graphs
#define FX 92         // node feature dim
#define FE 41         // edge feature dim
#define HD 64         // hidden
#define NCV 3         // conv layers
#define BN_EPS 1e-5f
#define NBLK 196      // scan blocks: 196*256 = 50176 >= NN
#define EPT 128       // edges per tile

typedef unsigned long long ull;
typedef long long ll;

// ---------------- device scratch ----------------
__device__ float g_h[NN * HD];
__device__ float g_acc[NN * HD];
__device__ float g_HN[NN * 4 * HD];                   // [N,256]: [f_i|s_i|f_j|s_j]
__device__ float g_Wce[NCV * FE * 2 * HD];
__device__ float g_bce[NCV * 2 * HD];
__device__ float g_Wnode[NCV * HD * 4 * HD];
__device__ float g_sum[NCV * HD];
__device__ float g_sumsq[NCV * HD];
__device__ float g_gsum[NG * HD];
__device__ float g_gcnt[NG];
// sort-by-dst machinery
__device__ int   g_deg[NN];
__device__ int   g_cursor[NN];
__device__ int   g_rp[NN];
__device__ int   g_bsum[256];
__device__ int   g_perm[NE];
__device__ int   g_srcp[NE];
__device__ int   g_dstp[NE];
__device__ float g_eap[(ll)NE * FE];   // permuted edge_attr

// ---------------- helpers ----------------
__device__ __forceinline__ ull pack2(float a, float b) {
    ull r; asm("mov.b64 %0, {%1, %2};" : "=l"(r) : "f"(a), "f"(b)); return r;
}
__device__ __forceinline__ void unpack2(ull v, float& a, float& b) {
    asm("mov.b64 {%0, %1}, %2;" : "=f"(a), "=f"(b) : "l"(v));
}
__device__ __forceinline__ void fma2(ull& d, ull a, ull b) {
    asm("fma.rn.f32x2 %0, %1, %2, %0;" : "+l"(d) : "l"(a), "l"(b));
}
// sigmoid(x) = 0.5*tanh(0.5x)+0.5  (1 MUFU instead of 2)
__device__ __forceinline__ float sigmoid_f(float x) {
    float t;
    asm("tanh.approx.f32 %0, %1;" : "=f"(t) : "f"(x * 0.5f));
    return fmaf(t, 0.5f, 0.5f);
}
__device__ __forceinline__ float softplus_f(float x) {
    return fmaxf(x, 0.0f) + __logf(1.0f + __expf(-fabsf(x)));
}
__device__ __forceinline__ void red4(float* p, float4 v) {
    asm volatile("red.global.add.v4.f32 [%0], {%1,%2,%3,%4};"
                 :: "l"(p), "f"(v.x), "f"(v.y), "f"(v.z), "f"(v.w) : "memory");
}
__device__ __forceinline__ void red2(float* p, float a, float b) {
    asm volatile("red.global.add.v2.f32 [%0], {%1,%2};"
                 :: "l"(p), "f"(a), "f"(b) : "memory");
}
__device__ __forceinline__ uint32_t to_tf32(float f) {
    uint32_t r; asm("cvt.rna.tf32.f32 %0, %1;" : "=r"(r) : "f"(f)); return r;
}
__device__ __forceinline__ void mma_tf32(float c[4], uint32_t a0, uint32_t a1,
                                         uint32_t a2, uint32_t a3,
                                         uint32_t b0, uint32_t b1) {
    asm volatile(
        "mma.sync.aligned.m16n8k8.row.col.f32.tf32.tf32.f32 "
        "{%0,%1,%2,%3}, {%4,%5,%6,%7}, {%8,%9}, {%0,%1,%2,%3};"
        : "+f"(c[0]), "+f"(c[1]), "+f"(c[2]), "+f"(c[3])
        : "r"(a0), "r"(a1), "r"(a2), "r"(a3), "r"(b0), "r"(b1));
}

// ---------------- prep: fold weights ----------------
__global__ void prep_kernel(const float* __restrict__ W_emb2, const float* __restrict__ b_emb2,
                            const float* __restrict__ Wf, const float* __restrict__ bf,
                            const float* __restrict__ Ws, const float* __restrict__ bs) {
    int idx = blockIdx.x * blockDim.x + threadIdx.x;
    const int N_WCE = NCV * FE * 2 * HD;
    const int N_BCE = NCV * 2 * HD;
    const int N_WND = NCV * HD * 4 * HD;
    if (idx < N_WCE) {
        int j = idx % (2 * HD);
        int k = (idx / (2 * HD)) % FE;
        int a = idx / (2 * HD * FE);
        const float* Wb = (j < HD) ? Wf : Ws;
        int jj = j & (HD - 1);
        float s = 0.f;
        #pragma unroll 8
        for (int m = 0; m < HD; m++)
            s = fmaf(W_emb2[k * HD + m], Wb[(a * 3 * HD + 2 * HD + m) * HD + jj], s);
        g_Wce[idx] = s;
    } else if (idx < N_WCE + N_BCE) {
        int t = idx - N_WCE;
        int j = t % (2 * HD);
        int a = t / (2 * HD);
        const float* Wb = (j < HD) ? Wf : Ws;
        const float* bb = (j < HD) ? bf : bs;
        int jj = j & (HD - 1);
        float s = bb[a * HD + jj];
        #pragma unroll 8
        for (int m = 0; m < HD; m++)
            s = fmaf(b_emb2[m], Wb[(a * 3 * HD + 2 * HD + m) * HD + jj], s);
        g_bce[t] = s;
    } else if (idx < N_WCE + N_BCE + N_WND) {
        int t = idx - N_WCE - N_BCE;
        int j = t % (4 * HD);
        int m = (t / (4 * HD)) % HD;
        int a = t / (4 * HD * HD);
        int blk = j / HD;                 // 0:f_i 1:s_i 2:f_j 3:s_j
        int jj = j & (HD - 1);
        const float* Wsel = (blk & 1) ? Ws : Wf;
        int roff = (blk >= 2) ? HD : 0;
        g_Wnode[t] = Wsel[(a * 3 * HD + roff + m) * HD + jj];
    }
}

// ---------------- zero counters/stats ----------------
__global__ void zero_kernel() {
    int i = blockIdx.x * blockDim.x + threadIdx.x;
    if (i < NN) { g_deg[i] = 0; g_cursor[i] = 0; }
    if (i < NCV * HD) { g_sum[i] = 0.f; g_sumsq[i] = 0.f; }
    if (i < NG * HD) g_gsum[i] = 0.f;
    if (i < NG) g_gcnt[i] = 0.f;
}

// ---------------- sort by dst ----------------
__global__ void hist_kernel(const int* __restrict__ ei) {
    int e = blockIdx.x * blockDim.x + threadIdx.x;
    if (e < NE) atomicAdd(&g_deg[ei[NE + e]], 1);
}
__global__ void scan1_kernel() {
    __shared__ int s[256];
    int tid = threadIdx.x;
    int i = blockIdx.x * 256 + tid;
    int v = (i < NN) ? g_deg[i] : 0;
    s[tid] = v; __syncthreads();
    #pragma unroll
    for (int off = 1; off < 256; off <<= 1) {
        int t = (tid >= off) ? s[tid - off] : 0;
        __syncthreads();
        s[tid] += t;
        __syncthreads();
    }
    if (i < NN) g_rp[i] = s[tid] - v;
    if (tid == 255) g_bsum[blockIdx.x] = s[255];
}
__global__ void scan2_kernel() {
    __shared__ int s[256];
    int tid = threadIdx.x;
    int v = (tid < NBLK) ? g_bsum[tid] : 0;
    s[tid] = v; __syncthreads();
    #pragma unroll
    for (int off = 1; off < 256; off <<= 1) {
        int t = (tid >= off) ? s[tid - off] : 0;
        __syncthreads();
        s[tid] += t;
        __syncthreads();
    }
    if (tid < NBLK) g_bsum[tid] = s[tid] - v;
}
__global__ void scan3_kernel() {
    int i = blockIdx.x * 256 + threadIdx.x;
    if (i < NN) g_rp[i] += g_bsum[blockIdx.x];
}
__global__ void scatter_kernel(const int* __restrict__ ei) {
    int e = blockIdx.x * blockDim.x + threadIdx.x;
    if (e >= NE) return;
    int d = ei[NE + e];
    int s = ei[e];
    int pos = g_rp[d] + atomicAdd(&g_cursor[d], 1);
    g_perm[pos] = e;
    g_srcp[pos] = s;
    g_dstp[pos] = d;
}
__global__ void permute_ea_kernel(const float* __restrict__ ea) {
    int w = (blockIdx.x * blockDim.x + threadIdx.x) >> 5;
    int lane = threadIdx.x & 31;
    int nw = (gridDim.x * blockDim.x) >> 5;
    for (int row = w; row < NE; row += nw) {
        int e = g_perm[row];
        for (int k = lane; k < FE; k += 32)
            g_eap[(ll)row * FE + k] = ea[(ll)e * FE + k];
    }
}

// ---------------- generic fp32 GEMM with f32x2 inner loop ----------------
template <int K, int NC, int CT, int RT, int RPT>
__global__ void gemm_bias_kernel(const float* __restrict__ A, const float* __restrict__ B,
                                 const float* __restrict__ bias, float* __restrict__ C,
                                 int M, int ldb, int ldc) {
    constexpr int TR = RT * RPT;
    constexpr int KP = K + 1;
    constexpr int NT = CT * RT;
    extern __shared__ float smem[];
    float* Bs = smem;
    float* As = smem + K * NC;
    int tid = threadIdx.x;
    int tx = tid % CT;
    int ty = tid / CT;
    int c0 = blockIdx.y * NC;
    for (int i = tid; i < K * NC; i += NT) {
        int k = i / NC, c = i - k * NC;
        Bs[i] = B[k * ldb + c0 + c];
    }
    ull bp[NC / CT / 2];
    #pragma unroll
    for (int c = 0; c < NC / CT / 2; c++) {
        float b0 = bias ? bias[c0 + tx * 8 + 2 * c] : 0.f;
        float b1 = bias ? bias[c0 + tx * 8 + 2 * c + 1] : 0.f;
        bp[c] = pack2(b0, b1);
    }
    for (int tile = blockIdx.x; (ll)tile * TR < M; tile += gridDim.x) {
        int row0 = tile * TR;
        __syncthreads();
        for (int i = tid; i < TR * K; i += NT) {
            int r = i / K;
            int k = i - r * K;
            int gr = row0 + r;
            As[r * KP + k] = (gr < M) ? A[(ll)gr * K + k] : 0.f;
        }
        __syncthreads();
        ull acc[RPT][4];
        #pragma unroll
        for (int r = 0; r < RPT; r++)
            #pragma unroll
            for (int c = 0; c < 4; c++) acc[r][c] = bp[c];
        for (int k = 0; k < K; k++) {
            float4 b0 = *reinterpret_cast<const float4*>(&Bs[k * NC + tx * 8]);
            float4 b1 = *reinterpret_cast<const float4*>(&Bs[k * NC + tx * 8 + 4]);
            ull p0 = pack2(b0.x, b0.y), p1 = pack2(b0.z, b0.w);
            ull p2 = pack2(b1.x, b1.y), p3 = pack2(b1.z, b1.w);
            #pragma unroll
            for (int r = 0; r < RPT; r++) {
                float a = As[(ty * RPT + r) * KP + k];
                ull ad = pack2(a, a);
                fma2(acc[r][0], ad, p0);
                fma2(acc[r][1], ad, p1);
                fma2(acc[r][2], ad, p2);
                fma2(acc[r][3], ad, p3);
            }
        }
        #pragma unroll
        for (int r = 0; r < RPT; r++) {
            int gr = row0 + ty * RPT + r;
            if (gr < M) {
                float o[8];
                #pragma unroll
                for (int c = 0; c < 4; c++) unpack2(acc[r][c], o[2 * c], o[2 * c + 1]);
                float* cp = &C[(ll)gr * ldc + c0 + tx * 8];
                *reinterpret_cast<float4*>(cp) = make_float4(o[0], o[1], o[2], o[3]);
                *reinterpret_cast<float4*>(cp + 4) = make_float4(o[4], o[5], o[6], o[7]);
            }
        }
    }
}

// ---------------- residual copy ----------------
__global__ void copy_kernel() {
    int idx4 = blockIdx.x * blockDim.x + threadIdx.x;
    if (idx4 < NN * 16)
        reinterpret_cast<float4*>(g_acc)[idx4] = reinterpret_cast<const float4*>(g_h)[idx4];
}

// ---------------- fused: mma.sync tf32 edge GEMM + message + CSR scatter ----------------
// smem layout (bytes):
//   [0,512)       bias[128]
//   [512,1024)    src[128]
//   [1024,1536)   dst[128]
//   [1536, +3072*8)     Bp: prepacked B fragments   (24576B, persistent)
//   [26112, ...)        OVERLAPPED region:
//        At (48*136*4 = 26112B)  -- live: staging .. mma k-loop
//        EW (128*132*4 = 67584B) -- live: mma store .. message phase
#define AT_LD  136
#define EW_LD  132
#define SM_BP  1536
#define SM_AT  (SM_BP + 3072 * 8)          // 26112
#define SM_EW  SM_AT                        // overlapped with At
#define FE_SMEM (SM_AT + EPT * EW_LD * 4)  // 93696

__global__ __launch_bounds__(256, 2) void fused_edge_kernel(
        const float* __restrict__ Wce, const float* __restrict__ bce) {
    extern __shared__ char base[];
    float*    bias_s = (float*)(base);
    int*      src_s  = (int*)(base + 512);
    int*      dst_s  = (int*)(base + 1024);
    uint2*    Bp     = (uint2*)(base + SM_BP);
    uint32_t* At     = (uint32_t*)(base + SM_AT);
    float*    EW_s   = (float*)(base + SM_EW);

    int tid = threadIdx.x;
    int lane = tid & 31, wid = tid >> 5;
    int gid = lane >> 2, tig = lane & 3;

    if (tid < 128) bias_s[tid] = bce[tid];
    // prepack B fragments: Bp[(kk*16+nt)*32+lane] = {B[8kk+tig][8nt+gid], B[8kk+tig+4][8nt+gid]}
    for (int i = tid; i < 3072; i += 256) {
        int l = i & 31, nt = (i >> 5) & 15, kk = i >> 9;
        int g = l >> 2, t = l & 3;
        int k0 = 8 * kk + t, k1 = k0 + 4, n = 8 * nt + g;
        uint32_t b0 = (k0 < FE) ? to_tf32(Wce[k0 * 128 + n]) : 0u;
        uint32_t b1 = (k1 < FE) ? to_tf32(Wce[k1 * 128 + n]) : 0u;
        Bp[i] = make_uint2(b0, b1);
    }

    const int ntiles = NE / EPT;   // 6250
    int row0 = wid * 16;
    for (int tile = blockIdx.x; tile < ntiles; tile += gridDim.x) {
        int e0 = tile * EPT;
        __syncthreads();   // prev msg phase done before At (=EW region) overwrite
        // stage A transposed + tf32-converted: At[k][e]; re-zero k-padding each tile
        for (int i = tid; i < EPT * FE; i += 256) {
            int r = i / FE, k = i - r * FE;
            At[k * AT_LD + r] = to_tf32(g_eap[(ll)e0 * FE + i]);
        }
        for (int i = tid; i < 7 * AT_LD; i += 256) At[FE * AT_LD + i] = 0u;
        if (tid < EPT) {
            src_s[tid] = g_srcp[e0 + tid];
            dst_s[tid] = g_dstp[e0 + tid];
        }
        __syncthreads();

        // ---- mma phase: warp computes rows [row0,row0+16) x 128 cols ----
        {
            float c[16][4];
            #pragma unroll
            for (int nt = 0; nt < 16; nt++)
                #pragma unroll
                for (int q = 0; q < 4; q++) c[nt][q] = 0.f;
            #pragma unroll
            for (int kk = 0; kk < 6; kk++) {
                uint32_t a0 = At[(8 * kk + tig) * AT_LD + row0 + gid];
                uint32_t a1 = At[(8 * kk + tig) * AT_LD + row0 + gid + 8];
                uint32_t a2 = At[(8 * kk + tig + 4) * AT_LD + row0 + gid];
                uint32_t a3 = At[(8 * kk + tig + 4) * AT_LD + row0 + gid + 8];
                #pragma unroll
                for (int nt = 0; nt < 16; nt++) {
                    uint2 b = Bp[(kk * 16 + nt) * 32 + lane];
                    mma_tf32(c[nt], a0, a1, a2, a3, b.x, b.y);
                }
            }
            __syncthreads();   // all At reads complete before EW overwrites region
            // store C + bias to EW (transpose to row-major per edge)
            #pragma unroll
            for (int nt = 0; nt < 16; nt++) {
                float2 bi = *reinterpret_cast<const float2*>(&bias_s[nt * 8 + 2 * tig]);
                *reinterpret_cast<float2*>(&EW_s[(row0 + gid) * EW_LD + nt * 8 + 2 * tig]) =
                    make_float2(c[nt][0] + bi.x, c[nt][1] + bi.y);
                *reinterpret_cast<float2*>(&EW_s[(row0 + gid + 8) * EW_LD + nt * 8 + 2 * tig]) =
                    make_float2(c[nt][2] + bi.x, c[nt][3] + bi.y);
            }
        }
        __syncthreads();

        // ---- message phase: warp handles edges [row0,row0+16), run-compressed ----
        {
            float2 fj[16], sj[16];
            #pragma unroll
            for (int r = 0; r < 16; r++) {
                int s = src_s[row0 + r];
                fj[r] = *reinterpret_cast<const float2*>(&g_HN[(ll)s * 256 + 128 + 2 * lane]);
                sj[r] = *reinterpret_cast<const float2*>(&g_HN[(ll)s * 256 + 192 + 2 * lane]);
            }
            int dprev = -1;
            float fi0 = 0.f, fi1 = 0.f, si0 = 0.f, si1 = 0.f, a0 = 0.f, a1 = 0.f;
            #pragma unroll
            for (int r = 0; r < 16; r++) {
                int e = row0 + r;
                int d = dst_s[e];   // warp-uniform
                if (d != dprev) {
                    if (dprev >= 0) red2(&g_acc[(ll)dprev * HD + 2 * lane], a0, a1);
                    float2 t0 = *reinterpret_cast<const float2*>(&g_HN[(ll)d * 256 + 2 * lane]);
                    float2 t1 = *reinterpret_cast<const float2*>(&g_HN[(ll)d * 256 + 64 + 2 * lane]);
                    fi0 = t0.x; fi1 = t0.y; si0 = t1.x; si1 = t1.y;
                    a0 = 0.f; a1 = 0.f;
                    dprev = d;
                }
                float2 ef = *reinterpret_cast<const float2*>(&EW_s[e * EW_LD + 2 * lane]);
                float2 es = *reinterpret_cast<const float2*>(&EW_s[e * EW_LD + 64 + 2 * lane]);
                a0 += sigmoid_f(ef.x + fi0 + fj[r].x) * softplus_f(es.x + si0 + sj[r].x);
                a1 += sigmoid_f(ef.y + fi1 + fj[r].y) * softplus_f(es.y + si1 + sj[r].y);
            }
            if (dprev >= 0) red2(&g_acc[(ll)dprev * HD + 2 * lane], a0, a1);
        }
    }
}

// ---------------- BN stats ----------------
__global__ void stats_kernel(int a) {
    __shared__ float s_s[HD], s_q[HD];
    int tid = threadIdx.x;
    if (tid < HD) { s_s[tid] = 0.f; s_q[tid] = 0.f; }
    __syncthreads();
    int col4 = tid & 15;
    float4 ls = make_float4(0.f, 0.f, 0.f, 0.f), lq = ls;
    const float4* acc4 = reinterpret_cast<const float4*>(g_acc);
    for (int idx4 = blockIdx.x * blockDim.x + tid; idx4 < NN * 16; idx4 += gridDim.x * blockDim.x) {
        float4 v = acc4[idx4];
        ls.x += v.x; lq.x = fmaf(v.x, v.x, lq.x);
        ls.y += v.y; lq.y = fmaf(v.y, v.y, lq.y);
        ls.z += v.z; lq.z = fmaf(v.z, v.z, lq.z);
        ls.w += v.w; lq.w = fmaf(v.w, v.w, lq.w);
    }
    atomicAdd(&s_s[col4 * 4 + 0], ls.x); atomicAdd(&s_q[col4 * 4 + 0], lq.x);
    atomicAdd(&s_s[col4 * 4 + 1], ls.y); atomicAdd(&s_q[col4 * 4 + 1], lq.y);
    atomicAdd(&s_s[col4 * 4 + 2], ls.z); atomicAdd(&s_q[col4 * 4 + 2], lq.z);
    atomicAdd(&s_s[col4 * 4 + 3], ls.w); atomicAdd(&s_q[col4 * 4 + 3], lq.w);
    __syncthreads();
    if (tid < HD) {
        atomicAdd(&g_sum[a * HD + tid], s_s[tid]);
        atomicAdd(&g_sumsq[a * HD + tid], s_q[tid]);
    }
}

// ---------------- BN normalize (+relu) (+next residual) (+pooling) ----------------
__global__ void bn_kernel(const float* __restrict__ gamma, const float* __restrict__ beta,
                          int a, int do_relu, int write_acc, int do_pool,
                          const int* __restrict__ batch) {
    int idx4 = blockIdx.x * blockDim.x + threadIdx.x;
    if (idx4 >= NN * 16) return;
    int col4 = idx4 & 15;
    int node = idx4 >> 4;
    const float invn = 1.0f / (float)NN;
    float4 su = reinterpret_cast<const float4*>(g_sum)[a * 16 + col4];
    float4 sq = reinterpret_cast<const float4*>(g_sumsq)[a * 16 + col4];
    float4 ga = reinterpret_cast<const float4*>(gamma)[col4];
    float4 be = reinterpret_cast<const float4*>(beta)[col4];
    float4 v = reinterpret_cast<const float4*>(g_acc)[idx4];
    #pragma unroll
    for (int c = 0; c < 4; c++) {
        float mu = (&su.x)[c] * invn;
        float var = fmaxf((&sq.x)[c] * invn - mu * mu, 0.f);
        float y = ((&v.x)[c] - mu) * rsqrtf(var + BN_EPS) * (&ga.x)[c] + (&be.x)[c];
        if (do_relu) y = fmaxf(y, 0.f);
        (&v.x)[c] = y;
    }
    reinterpret_cast<float4*>(g_h)[idx4] = v;
    if (write_acc) reinterpret_cast<float4*>(g_acc)[idx4] = v;
    if (do_pool) {
        int b = batch[node];
        red4(&g_gsum[b * HD + col4 * 4], v);
        if (col4 == 0) atomicAdd(&g_gcnt[b], 1.0f);
    }
}

// ---------------- final MLP ----------------
__global__ void mlp_kernel(const float* __restrict__ W1, const float* __restrict__ b1,
                           const float* __restrict__ W2, const float* __restrict__ b2,
                           const float* __restrict__ Wo, const float* __restrict__ bo,
                           float* __restrict__ out) {
    __shared__ float sW1[HD * HD], sW2[HD * HD], sWo[HD], sb1[HD], sb2[HD];
    int tid = threadIdx.x;
    for (int i = tid; i < HD * HD; i += blockDim.x) { sW1[i] = W1[i]; sW2[i] = W2[i]; }
    if (tid < HD) { sWo[tid] = Wo[tid]; sb1[tid] = b1[tid]; sb2[tid] = b2[tid]; }
    __syncthreads();
    if (tid < NG) {
        float inv = 1.0f / fmaxf(g_gcnt[tid], 1.0f);
        float v[HD], y[HD];
        #pragma unroll
        for (int k = 0; k < HD; k++) v[k] = g_gsum[tid * HD + k] * inv;
        #pragma unroll 1
        for (int j = 0; j < HD; j++) {
            float s = sb1[j];
            #pragma unroll
            for (int k = 0; k < HD; k++) s = fmaf(v[k], sW1[k * HD + j], s);
            y[j] = fmaxf(s, 0.0f) + __logf(1.0f + __expf(-fabsf(s)));
        }
        float o = bo[0];
        #pragma unroll 1
        for (int j = 0; j < HD; j++) {
            float s = sb2[j];
            #pragma unroll
            for (int k = 0; k < HD; k++) s = fmaf(y[k], sW2[k * HD + j], s);
            o = fmaf(fmaxf(s, 0.0f) + __logf(1.0f + __expf(-fabsf(s))), sWo[j], o);
        }
        out[tid] = o;
    }
}

// ---------------- host launcher ----------------
template <int K, int NC, int CT, int RT, int RPT>
static void launch_gemm(const float* A, const float* B, const float* bias, float* C,
                        int M, int ldb, int ldc, int nsplit) {
    constexpr int TR = RT * RPT;
    constexpr int KP = K + 1;
    static_assert(CT * 8 == NC, "col threads x 8 must equal NC");
    size_t sm = (size_t)(K * NC + TR * KP) * sizeof(float);
    if (sm > 48 * 1024) {
        cudaFuncSetAttribute(gemm_bias_kernel<K, NC, CT, RT, RPT>,
                             cudaFuncAttributeMaxDynamicSharedMemorySize, (int)sm);
    }
    dim3 grid((M + TR - 1) / TR, nsplit);
    gemm_bias_kernel<K, NC, CT, RT, RPT><<<grid, CT * RT, sm>>>(A, B, bias, C, M, ldb, ldc);
}

extern "C" void kernel_launch(void* const* d_in, const int* in_sizes, int n_in,
                              void* d_out, int out_size) {
    const float* x         = (const float*)d_in[0];
    const float* edge_attr = (const float*)d_in[1];
    const int*   ei        = (const int*)d_in[2];
    const int*   batch     = (const int*)d_in[3];
    const float* W_emb1    = (const float*)d_in[4];
    const float* b_emb1    = (const float*)d_in[5];
    const float* W_emb2    = (const float*)d_in[6];
    const float* b_emb2    = (const float*)d_in[7];
    const float* Wf        = (const float*)d_in[8];
    const float* bf        = (const float*)d_in[9];
    const float* Ws        = (const float*)d_in[10];
    const float* bs        = (const float*)d_in[11];
    const float* gamma     = (const float*)d_in[12];
    const float* beta      = (const float*)d_in[13];
    const float* W1        = (const float*)d_in[14];
    const float* b1        = (const float*)d_in[15];
    const float* W2        = (const float*)d_in[16];
    const float* b2        = (const float*)d_in[17];
    const float* Wo        = (const float*)d_in[18];
    const float* bo        = (const float*)d_in[19];
    float* out = (float*)d_out;

    float *p_h, *p_Wce, *p_bce, *p_Wnode, *p_HN;
    cudaGetSymbolAddress((void**)&p_h, g_h);
    cudaGetSymbolAddress((void**)&p_Wce, g_Wce);
    cudaGetSymbolAddress((void**)&p_bce, g_bce);
    cudaGetSymbolAddress((void**)&p_Wnode, g_Wnode);
    cudaGetSymbolAddress((void**)&p_HN, g_HN);

    // fold weights + zero counters/stats
    prep_kernel<<<255, 256>>>(W_emb2, b_emb2, Wf, bf, Ws, bs);
    zero_kernel<<<NBLK, 256>>>();

    // sort edges by dst (counting sort) + permute edge_attr
    hist_kernel<<<(NE + 255) / 256, 256>>>(ei);
    scan1_kernel<<<NBLK, 256>>>();
    scan2_kernel<<<1, 256>>>();
    scan3_kernel<<<NBLK, 256>>>();
    scatter_kernel<<<(NE + 255) / 256, 256>>>(ei);
    permute_ea_kernel<<<1600, 256>>>(edge_attr);

    // h0 = x @ W_emb1 + b_emb1
    launch_gemm<FX, HD, 8, 32, 4>(x, W_emb1, b_emb1, p_h, NN, HD, HD, 1);
    copy_kernel<<<(NN * 16 + 255) / 256, 256>>>();

    cudaFuncSetAttribute(fused_edge_kernel,
                         cudaFuncAttributeMaxDynamicSharedMemorySize, FE_SMEM);

    for (int a = 0; a < NCV; a++) {
        // HN = h @ Wnode[a], 4 column chunks of 64 (smem 49KB -> better occupancy)
        launch_gemm<HD, HD, 8, 32, 4>(p_h, p_Wnode + (ll)a * HD * 4 * HD,
                                      nullptr, p_HN, NN, 4 * HD, 4 * HD, 4);
        fused_edge_kernel<<<296, 256, FE_SMEM>>>(p_Wce + a * FE * 2 * HD,
                                                 p_bce + a * 2 * HD);
        stats_kernel<<<296, 256>>>(a);
        bn_kernel<<<(NN * 16 + 255) / 256, 256>>>(gamma + a * HD, beta + a * HD, a,
                                                  a < NCV - 1 ? 1 : 0,
                                                  a < NCV - 1 ? 1 : 0,
                                                  a == NCV - 1 ? 1 : 0, batch);
    }

    mlp_kernel<<<1, 128>>>(W1, b1, W2, b2, Wo, bo, out);
}